// round 1
// baseline (speedup 1.0000x reference)
#include <cuda_runtime.h>

#define NNODE 50000
#define NEDGE 800000
#define H 128
#define LNUM 4
#define HPAD 50048            // 391 * 128, padded row count for guard-free tiles
#define BN_EPS 1e-5f

// ---------------- device scratch (allocation-free rule: __device__ globals) ---
__device__ int   g_counts[NNODE];
__device__ int   g_cursor[NNODE];
__device__ int   g_offs[NNODE + 1];
__device__ int   g_ssrc[NEDGE];
__device__ float g_h [(size_t)HPAD * H];
__device__ float g_t1[(size_t)HPAD * H];
__device__ float g_t2[(size_t)HPAD * H];
__device__ float g_accs[H];
__device__ float g_accq[H];
__device__ float g_ta[H];
__device__ float g_ts[H];

// ---------------- helpers ----------------------------------------------------
__device__ __forceinline__ float4 f4zero() { return make_float4(0.f, 0.f, 0.f, 0.f); }
__device__ __forceinline__ void f4add(float4& a, const float4 b) {
    a.x += b.x; a.y += b.y; a.z += b.z; a.w += b.w;
}
__device__ __forceinline__ float4 f4affine_relu(float4 v, float4 a, float4 s) {
    float4 r;
    r.x = fmaxf(fmaf(a.x, v.x, s.x), 0.f);
    r.y = fmaxf(fmaf(a.y, v.y, s.y), 0.f);
    r.z = fmaxf(fmaf(a.z, v.z, s.z), 0.f);
    r.w = fmaxf(fmaf(a.w, v.w, s.w), 0.f);
    return r;
}

// ---------------- CSR build ---------------------------------------------------
__global__ void zero_k() {
    int i = blockIdx.x * blockDim.x + threadIdx.x;
    if (i < NNODE) g_counts[i] = 0;
    if (i < H) { g_accs[i] = 0.f; g_accq[i] = 0.f; }
}

__global__ void hist_k(const int* __restrict__ dst) {
    int e = blockIdx.x * blockDim.x + threadIdx.x;
    if (e < NEDGE) atomicAdd(&g_counts[dst[e]], 1);
}

__global__ void scan_k() {
    __shared__ int wsum[32];
    __shared__ int carry;
    int t = threadIdx.x;
    if (t == 0) carry = 0;
    __syncthreads();
    for (int base = 0; base < NNODE; base += 1024) {
        int i = base + t;
        int v = (i < NNODE) ? g_counts[i] : 0;
        int x = v;
        #pragma unroll
        for (int d = 1; d < 32; d <<= 1) {
            int y = __shfl_up_sync(0xffffffffu, x, d);
            if ((t & 31) >= d) x += y;
        }
        if ((t & 31) == 31) wsum[t >> 5] = x;
        __syncthreads();
        if (t < 32) {
            int y = wsum[t];
            #pragma unroll
            for (int d = 1; d < 32; d <<= 1) {
                int z = __shfl_up_sync(0xffffffffu, y, d);
                if (t >= d) y += z;
            }
            wsum[t] = y;
        }
        __syncthreads();
        int incl = x + ((t >= 32) ? wsum[(t >> 5) - 1] : 0);
        int excl = carry + incl - v;
        if (i < NNODE) { g_offs[i] = excl; g_cursor[i] = excl; }
        int tot = wsum[31];
        __syncthreads();
        if (t == 0) carry += tot;
        __syncthreads();
    }
    if (t == 0) g_offs[NNODE] = NEDGE;
}

__global__ void fill_k(const int* __restrict__ ei) {
    int e = blockIdx.x * blockDim.x + threadIdx.x;
    if (e < NEDGE) {
        int d = ei[NEDGE + e];          // dst row of edge_index [2, E]
        int pos = atomicAdd(&g_cursor[d], 1);
        g_ssrc[pos] = ei[e];            // src
    }
}

// ---------------- aggregation: h = T(x_v) + sum_{j in N(v)} T(x_j) ------------
// T = identity (layer 0, external x) or fused affine+ReLU over g_t2.
template <bool TRANS>
__global__ __launch_bounds__(256) void agg_k(const float* __restrict__ xext) {
    const float* in = TRANS ? (const float*)g_t2 : xext;
    int t = threadIdx.x;
    int lane = t & 31;
    int node = blockIdx.x * 8 + (t >> 5);
    if (node >= HPAD) return;
    int cb = lane * 4;
    float4* outp = (float4*)(g_h + (size_t)node * H + cb);
    if (node >= NNODE) { *outp = f4zero(); return; }

    float4 Aa = f4zero(), Ss = f4zero();
    if (TRANS) {
        Aa = *(const float4*)(g_ta + cb);
        Ss = *(const float4*)(g_ts + cb);
    }

    float4 a0, a1 = f4zero(), a2 = f4zero(), a3 = f4zero();
    {
        float4 v = *(const float4*)(in + (size_t)node * H + cb);
        a0 = TRANS ? f4affine_relu(v, Aa, Ss) : v;
    }
    int j = g_offs[node];
    int jend = g_offs[node + 1];
    for (; j + 3 < jend; j += 4) {
        int s0 = g_ssrc[j], s1 = g_ssrc[j + 1], s2 = g_ssrc[j + 2], s3 = g_ssrc[j + 3];
        float4 v0 = *(const float4*)(in + (size_t)s0 * H + cb);
        float4 v1 = *(const float4*)(in + (size_t)s1 * H + cb);
        float4 v2 = *(const float4*)(in + (size_t)s2 * H + cb);
        float4 v3 = *(const float4*)(in + (size_t)s3 * H + cb);
        if (TRANS) {
            v0 = f4affine_relu(v0, Aa, Ss); v1 = f4affine_relu(v1, Aa, Ss);
            v2 = f4affine_relu(v2, Aa, Ss); v3 = f4affine_relu(v3, Aa, Ss);
        }
        f4add(a0, v0); f4add(a1, v1); f4add(a2, v2); f4add(a3, v3);
    }
    for (; j < jend; ++j) {
        float4 v = *(const float4*)(in + (size_t)g_ssrc[j] * H + cb);
        if (TRANS) v = f4affine_relu(v, Aa, Ss);
        f4add(a0, v);
    }
    f4add(a0, a1); f4add(a2, a3); f4add(a0, a2);
    *outp = a0;
}

// ---------------- GEMM: out[n,o] = sum_k T(A[n,k]) * W[o,k] -------------------
// asel: 0=g_h, 1=g_t1, 2=g_t2.  osel: 0=g_t1, 1=g_t2, 2=oext (d_out).
// TRANS: per-column affine+ReLU (g_ta/g_ts) fused into A load.
// STATS: per-output-column sum/sumsq into g_accs/g_accq.
// BIAS:  add bias[o] on store.
template <bool TRANS, bool STATS, bool BIAS>
__global__ __launch_bounds__(256, 2) void gemm_k(int asel, const float* __restrict__ W,
                                                 int osel, float* __restrict__ oext,
                                                 const float* __restrict__ bias,
                                                 int storeN) {
    const float* A = (asel == 0) ? g_h : (asel == 1) ? g_t1 : g_t2;
    float* out = (osel == 0) ? g_t1 : (osel == 1) ? g_t2 : oext;

    __shared__ float As[16][132];
    __shared__ float Ws[16][136];
    __shared__ float Red[16][128];

    int t = threadIdx.x;
    int tx = t & 15;
    int ty = t >> 4;
    int m0 = blockIdx.x * 128;

    float acc[8][8];
    #pragma unroll
    for (int i = 0; i < 8; ++i)
        #pragma unroll
        for (int j = 0; j < 8; ++j) acc[i][j] = 0.f;

    #pragma unroll 1
    for (int p = 0; p < 8; ++p) {
        int k0 = p * 16;
        float4 va[2], vw[2];
        int arow[2], akq[2];
        #pragma unroll
        for (int hh = 0; hh < 2; ++hh) {
            int q = t + hh * 256;
            arow[hh] = q >> 2; akq[hh] = q & 3;
            int r = m0 + arow[hh];
            if (r < NNODE) {
                float4 v = *(const float4*)(A + (size_t)r * H + k0 + akq[hh] * 4);
                if (TRANS) {
                    float4 a4 = *(const float4*)(g_ta + k0 + akq[hh] * 4);
                    float4 s4 = *(const float4*)(g_ts + k0 + akq[hh] * 4);
                    v = f4affine_relu(v, a4, s4);
                }
                va[hh] = v;
            } else {
                va[hh] = f4zero();
            }
            vw[hh] = *(const float4*)(W + (size_t)arow[hh] * H + k0 + akq[hh] * 4);
        }
        __syncthreads();   // previous phase's smem reads finished
        #pragma unroll
        for (int hh = 0; hh < 2; ++hh) {
            As[akq[hh] * 4 + 0][arow[hh]] = va[hh].x;
            As[akq[hh] * 4 + 1][arow[hh]] = va[hh].y;
            As[akq[hh] * 4 + 2][arow[hh]] = va[hh].z;
            As[akq[hh] * 4 + 3][arow[hh]] = va[hh].w;
            Ws[akq[hh] * 4 + 0][arow[hh]] = vw[hh].x;
            Ws[akq[hh] * 4 + 1][arow[hh]] = vw[hh].y;
            Ws[akq[hh] * 4 + 2][arow[hh]] = vw[hh].z;
            Ws[akq[hh] * 4 + 3][arow[hh]] = vw[hh].w;
        }
        __syncthreads();
        #pragma unroll
        for (int kk = 0; kk < 16; ++kk) {
            float4 a0 = *(const float4*)&As[kk][ty * 8];
            float4 a1 = *(const float4*)&As[kk][ty * 8 + 4];
            float4 w0 = *(const float4*)&Ws[kk][tx * 8];
            float4 w1 = *(const float4*)&Ws[kk][tx * 8 + 4];
            float av[8] = {a0.x, a0.y, a0.z, a0.w, a1.x, a1.y, a1.z, a1.w};
            float wv[8] = {w0.x, w0.y, w0.z, w0.w, w1.x, w1.y, w1.z, w1.w};
            #pragma unroll
            for (int i = 0; i < 8; ++i)
                #pragma unroll
                for (int j = 0; j < 8; ++j)
                    acc[i][j] = fmaf(av[i], wv[j], acc[i][j]);
        }
    }

    if (STATS) {
        float ls[8], lq[8];
        #pragma unroll
        for (int j = 0; j < 8; ++j) {
            float s = 0.f, q = 0.f;
            #pragma unroll
            for (int i = 0; i < 8; ++i) { s += acc[i][j]; q = fmaf(acc[i][j], acc[i][j], q); }
            ls[j] = s; lq[j] = q;
        }
        __syncthreads();
        #pragma unroll
        for (int j = 0; j < 8; ++j) Red[ty][tx * 8 + j] = ls[j];
        __syncthreads();
        if (ty == 0) {
            #pragma unroll
            for (int j = 0; j < 8; ++j) {
                float s = 0.f;
                #pragma unroll
                for (int yy = 0; yy < 16; ++yy) s += Red[yy][tx * 8 + j];
                atomicAdd(&g_accs[tx * 8 + j], s);
            }
        }
        __syncthreads();
        #pragma unroll
        for (int j = 0; j < 8; ++j) Red[ty][tx * 8 + j] = lq[j];
        __syncthreads();
        if (ty == 0) {
            #pragma unroll
            for (int j = 0; j < 8; ++j) {
                float s = 0.f;
                #pragma unroll
                for (int yy = 0; yy < 16; ++yy) s += Red[yy][tx * 8 + j];
                atomicAdd(&g_accq[tx * 8 + j], s);
            }
        }
    }

    float4 b0 = f4zero(), b1 = f4zero();
    if (BIAS) {
        b0 = *(const float4*)(bias + tx * 8);
        b1 = *(const float4*)(bias + tx * 8 + 4);
    }
    #pragma unroll
    for (int i = 0; i < 8; ++i) {
        int r = m0 + ty * 8 + i;
        if (r < storeN) {
            float4 o0 = make_float4(acc[i][0], acc[i][1], acc[i][2], acc[i][3]);
            float4 o1 = make_float4(acc[i][4], acc[i][5], acc[i][6], acc[i][7]);
            if (BIAS) {
                o0.x += b0.x; o0.y += b0.y; o0.z += b0.z; o0.w += b0.w;
                o1.x += b1.x; o1.y += b1.y; o1.z += b1.z; o1.w += b1.w;
            }
            *(float4*)(out + (size_t)r * H + tx * 8) = o0;
            *(float4*)(out + (size_t)r * H + tx * 8 + 4) = o1;
        }
    }
}

// ---------------- BN coefficient kernels (1 block, 128 threads) ---------------
// relu(bn1(t1 + b1)): fc bias cancels inside training-mode BN.
__global__ void stats1_k(const float* __restrict__ g, const float* __restrict__ b) {
    int t = threadIdx.x;
    float mu = g_accs[t] * (1.f / NNODE);
    float var = g_accq[t] * (1.f / NNODE) - mu * mu;
    float a = g[t] * rsqrtf(var + BN_EPS);
    g_ta[t] = a;
    g_ts[t] = b[t] - mu * a;
    g_accs[t] = 0.f; g_accq[t] = 0.f;
}

// relu(bn3(bn2(t2 + b2))): bn2 output has exact mean bn2_b and variance
// (g2*r2)^2 * var, so bn3 composes analytically; b2 and bn2_b cancel.
__global__ void stats2_k(const float* __restrict__ g2, const float* __restrict__ g3,
                         const float* __restrict__ b3) {
    int t = threadIdx.x;
    float mu = g_accs[t] * (1.f / NNODE);
    float var = g_accq[t] * (1.f / NNODE) - mu * mu;
    float r2 = rsqrtf(var + BN_EPS);
    float gr = g2[t] * r2;
    float v3 = gr * gr * var;
    float A = gr * g3[t] * rsqrtf(v3 + BN_EPS);
    g_ta[t] = A;
    g_ts[t] = b3[t] - mu * A;
    g_accs[t] = 0.f; g_accq[t] = 0.f;
}

// ---------------- launch ------------------------------------------------------
extern "C" void kernel_launch(void* const* d_in, const int* in_sizes, int n_in,
                              void* d_out, int out_size) {
    const float* x     = (const float*)d_in[0];
    const int*   ei    = (const int*)  d_in[1];
    const float* fc1_w = (const float*)d_in[2];
    const float* bn1_g = (const float*)d_in[4];
    const float* bn1_b = (const float*)d_in[5];
    const float* fc2_w = (const float*)d_in[6];
    const float* bn2_g = (const float*)d_in[8];
    const float* bn3_g = (const float*)d_in[10];
    const float* bn3_b = (const float*)d_in[11];
    const float* fc_w  = (const float*)d_in[12];
    const float* fc_b  = (const float*)d_in[13];
    float* out = (float*)d_out;

    zero_k<<<(NNODE + 255) / 256, 256>>>();
    hist_k<<<(NEDGE + 255) / 256, 256>>>(ei + NEDGE);
    scan_k<<<1, 1024>>>();
    fill_k<<<(NEDGE + 255) / 256, 256>>>(ei);

    const int GEMM_GRID = HPAD / 128;   // 391
    const int AGG_GRID  = HPAD / 8;     // 6256

    for (int i = 0; i < LNUM; ++i) {
        if (i == 0) agg_k<false><<<AGG_GRID, 256>>>(x);
        else        agg_k<true ><<<AGG_GRID, 256>>>(nullptr);
        gemm_k<false, true, false><<<GEMM_GRID, 256>>>(0, fc1_w + (size_t)i * H * H, 0,
                                                       nullptr, nullptr, HPAD);
        stats1_k<<<1, 128>>>(bn1_g + i * H, bn1_b + i * H);
        gemm_k<true, true, false><<<GEMM_GRID, 256>>>(1, fc2_w + (size_t)i * H * H, 1,
                                                      nullptr, nullptr, HPAD);
        stats2_k<<<1, 128>>>(bn2_g + i * H, bn3_g + i * H, bn3_b + i * H);
    }
    gemm_k<true, false, true><<<GEMM_GRID, 256>>>(2, fc_w, 2, out, fc_b, NNODE);
}

// round 3
// speedup vs baseline: 1.6979x; 1.6979x over previous
#include <cuda_runtime.h>
#include <cuda_bf16.h>
#include <cstdint>

#define NNODE 50000
#define NEDGE 800000
#define H 128
#define LNUM 4
#define HPAD 50048            // 391 * 128
#define NPADC 53248           // 13 * 4096, padded counts for int4 scan
#define BN_EPS 1e-5f

// ---------------- device scratch (allocation-free rule: __device__ globals) ---
__device__ int   g_counts[NPADC];
__device__ int   g_cursor[NNODE];
__device__ int   g_offs[NNODE + 1];
__device__ int   g_ssrc[NEDGE];
__device__ float g_h [(size_t)HPAD * H];
__device__ float g_t1[(size_t)HPAD * H];
__device__ float g_t2[(size_t)HPAD * H];
__device__ float g_accs[H];
__device__ float g_accq[H];
__device__ float g_ta[H];
__device__ float g_ts[H];

// ---------------- helpers ----------------------------------------------------
__device__ __forceinline__ float4 f4zero() { return make_float4(0.f, 0.f, 0.f, 0.f); }
__device__ __forceinline__ void f4add(float4& a, const float4 b) {
    a.x += b.x; a.y += b.y; a.z += b.z; a.w += b.w;
}
__device__ __forceinline__ float4 f4affine_relu(float4 v, float4 a, float4 s) {
    float4 r;
    r.x = fmaxf(fmaf(a.x, v.x, s.x), 0.f);
    r.y = fmaxf(fmaf(a.y, v.y, s.y), 0.f);
    r.z = fmaxf(fmaf(a.z, v.z, s.z), 0.f);
    r.w = fmaxf(fmaf(a.w, v.w, s.w), 0.f);
    return r;
}
// split fp32 -> (bf16 hi | bf16 lo) packed in one 32-bit word (lo in high half)
__device__ __forceinline__ uint32_t pack_split(float v) {
    __nv_bfloat16 h = __float2bfloat16(v);
    float hf = __bfloat162float(h);
    __nv_bfloat16 l = __float2bfloat16(v - hf);
    return (uint32_t)__bfloat16_as_ushort(h) | ((uint32_t)__bfloat16_as_ushort(l) << 16);
}
__device__ __forceinline__ void mma_bf16(float d[4], const uint32_t a[4],
                                         uint32_t b0, uint32_t b1) {
    asm volatile(
        "mma.sync.aligned.m16n8k16.row.col.f32.bf16.bf16.f32 "
        "{%0,%1,%2,%3}, {%4,%5,%6,%7}, {%8,%9}, {%0,%1,%2,%3};\n"
        : "+f"(d[0]), "+f"(d[1]), "+f"(d[2]), "+f"(d[3])
        : "r"(a[0]), "r"(a[1]), "r"(a[2]), "r"(a[3]), "r"(b0), "r"(b1));
}

// ---------------- CSR build ---------------------------------------------------
__global__ void zero_k() {
    int i = blockIdx.x * blockDim.x + threadIdx.x;
    if (i < NNODE) g_counts[i] = 0;
    if (i < H) { g_accs[i] = 0.f; g_accq[i] = 0.f; }
}

__global__ void hist_k(const int* __restrict__ dst) {
    int e = blockIdx.x * blockDim.x + threadIdx.x;
    if (e < NEDGE) atomicAdd(&g_counts[dst[e]], 1);
}

// 1024-thread single-block scan, int4 per thread per iteration (13 iterations).
__global__ void scan_k() {
    __shared__ int wsum[32];
    __shared__ int carry_s;
    int t = threadIdx.x;
    int lane = t & 31;
    if (t == 0) carry_s = 0;
    __syncthreads();
    #pragma unroll 1
    for (int it = 0; it < NPADC / 4096; ++it) {
        int i4 = it * 4096 + t * 4;
        int4 c = *(const int4*)(g_counts + i4);   // pad region is always 0
        int s0 = c.x, s1 = s0 + c.y, s2 = s1 + c.z, s3 = s2 + c.w;
        int x = s3;
        #pragma unroll
        for (int d = 1; d < 32; d <<= 1) {
            int y = __shfl_up_sync(0xffffffffu, x, d);
            if (lane >= d) x += y;
        }
        if (lane == 31) wsum[t >> 5] = x;
        __syncthreads();
        if (t < 32) {
            int y = wsum[t];
            #pragma unroll
            for (int d = 1; d < 32; d <<= 1) {
                int z = __shfl_up_sync(0xffffffffu, y, d);
                if (t >= d) y += z;
            }
            wsum[t] = y;
        }
        __syncthreads();
        int base = carry_s + ((t >= 32) ? wsum[(t >> 5) - 1] : 0) + x - s3;
        if (i4 + 0 < NNODE) { g_offs[i4 + 0] = base;      g_cursor[i4 + 0] = base; }
        if (i4 + 1 < NNODE) { g_offs[i4 + 1] = base + s0; g_cursor[i4 + 1] = base + s0; }
        if (i4 + 2 < NNODE) { g_offs[i4 + 2] = base + s1; g_cursor[i4 + 2] = base + s1; }
        if (i4 + 3 < NNODE) { g_offs[i4 + 3] = base + s2; g_cursor[i4 + 3] = base + s2; }
        int tot = wsum[31];
        __syncthreads();
        if (t == 0) carry_s += tot;
        __syncthreads();
    }
    if (t == 0) g_offs[NNODE] = NEDGE;
}

__global__ void fill_k(const int* __restrict__ ei) {
    int e = blockIdx.x * blockDim.x + threadIdx.x;
    if (e < NEDGE) {
        int d = ei[NEDGE + e];          // dst row of edge_index [2, E]
        int pos = atomicAdd(&g_cursor[d], 1);
        g_ssrc[pos] = ei[e];            // src
    }
}

// ---------------- aggregation: h = T(x_v) + sum_{j in N(v)} T(x_j) ------------
template <bool TRANS>
__global__ __launch_bounds__(256) void agg_k(const float* __restrict__ xext) {
    const float* in = TRANS ? (const float*)g_t2 : xext;
    int t = threadIdx.x;
    int lane = t & 31;
    int node = blockIdx.x * 8 + (t >> 5);
    if (node >= HPAD) return;
    int cb = lane * 4;
    float4* outp = (float4*)(g_h + (size_t)node * H + cb);
    if (node >= NNODE) { *outp = f4zero(); return; }

    float4 Aa = f4zero(), Ss = f4zero();
    if (TRANS) {
        Aa = *(const float4*)(g_ta + cb);
        Ss = *(const float4*)(g_ts + cb);
    }

    float4 a0, a1 = f4zero(), a2 = f4zero(), a3 = f4zero();
    {
        float4 v = *(const float4*)(in + (size_t)node * H + cb);
        a0 = TRANS ? f4affine_relu(v, Aa, Ss) : v;
    }
    int j = g_offs[node];
    int jend = g_offs[node + 1];
    for (; j + 3 < jend; j += 4) {
        int s0 = g_ssrc[j], s1 = g_ssrc[j + 1], s2 = g_ssrc[j + 2], s3 = g_ssrc[j + 3];
        float4 v0 = *(const float4*)(in + (size_t)s0 * H + cb);
        float4 v1 = *(const float4*)(in + (size_t)s1 * H + cb);
        float4 v2 = *(const float4*)(in + (size_t)s2 * H + cb);
        float4 v3 = *(const float4*)(in + (size_t)s3 * H + cb);
        if (TRANS) {
            v0 = f4affine_relu(v0, Aa, Ss); v1 = f4affine_relu(v1, Aa, Ss);
            v2 = f4affine_relu(v2, Aa, Ss); v3 = f4affine_relu(v3, Aa, Ss);
        }
        f4add(a0, v0); f4add(a1, v1); f4add(a2, v2); f4add(a3, v3);
    }
    for (; j < jend; ++j) {
        float4 v = *(const float4*)(in + (size_t)g_ssrc[j] * H + cb);
        if (TRANS) v = f4affine_relu(v, Aa, Ss);
        f4add(a0, v);
    }
    f4add(a0, a1); f4add(a2, a3); f4add(a0, a2);
    *outp = a0;
}

// ---------------- tensor-core GEMM (bf16x3 split, m16n8k16) -------------------
// out[n,o] = sum_k T(A[n,k]) * W[o,k], fp32-accurate via hi/lo bf16 split:
//   x = hi + lo (both bf16);  x*y ~= hi*hi' + lo*hi' + hi*lo'
// Each smem word packs (hi | lo<<16); fragments built with LDS.64 + 2 PRMT.
// Block: 128 rows x full N=128, K=128 resident.  8 warps = 4(m) x 2(n).
#define SMP 136   // word pitch: (8g + 2tig) mod 32 conflict-free per half-warp
#define GEMM_SMEM_BYTES (2 * 128 * SMP * 4)

template <bool TRANS, bool STATS, bool BIAS>
__global__ __launch_bounds__(256, 1) void gemm_tc(int asel, const float* __restrict__ W,
                                                  int osel, float* __restrict__ oext,
                                                  const float* __restrict__ bias,
                                                  int storeN) {
    const float* A = (asel == 0) ? g_h : (asel == 1) ? g_t1 : g_t2;
    float* out = (osel == 0) ? g_t1 : (osel == 1) ? g_t2 : oext;

    extern __shared__ uint32_t sm[];
    uint32_t* As = sm;                    // [128][SMP] packed hi|lo
    uint32_t* Ws = sm + 128 * SMP;        // [128][SMP]

    int t = threadIdx.x;
    int m0 = blockIdx.x * 128;

    // ---- fill smem: A (optional affine+relu, row guard) and W, split-packed --
    #pragma unroll
    for (int j = 0; j < 16; ++j) {
        int idx = t + j * 256;
        int row = idx >> 5;          // 0..127
        int q = idx & 31;            // float4 index along K
        int gr = m0 + row;
        float4 v = f4zero();
        if (gr < NNODE) {
            v = *(const float4*)(A + (size_t)gr * H + q * 4);
            if (TRANS) {
                float4 a4 = *(const float4*)(g_ta + q * 4);
                float4 s4 = *(const float4*)(g_ts + q * 4);
                v = f4affine_relu(v, a4, s4);
            }
        }
        uint4 u = make_uint4(pack_split(v.x), pack_split(v.y),
                             pack_split(v.z), pack_split(v.w));
        *(uint4*)(As + row * SMP + q * 4) = u;

        float4 w = *(const float4*)(W + (size_t)row * H + q * 4);
        uint4 uw = make_uint4(pack_split(w.x), pack_split(w.y),
                              pack_split(w.z), pack_split(w.w));
        *(uint4*)(Ws + row * SMP + q * 4) = uw;
    }
    __syncthreads();

    int lane = t & 31;
    int w = t >> 5;
    int wm = w & 3;          // m-warp 0..3  (rows wm*32)
    int wn = w >> 2;         // n-warp 0..1  (cols wn*64)
    int g = lane >> 2;
    int tig = lane & 3;
    int mb = wm * 32;
    int nb = wn * 64;

    float d[2][8][4];
    #pragma unroll
    for (int mt = 0; mt < 2; ++mt)
        #pragma unroll
        for (int nt = 0; nt < 8; ++nt)
            #pragma unroll
            for (int i = 0; i < 4; ++i) d[mt][nt][i] = 0.f;

    #pragma unroll
    for (int ks = 0; ks < 8; ++ks) {
        int k0 = ks * 16;
        uint32_t ah[2][4], al[2][4];
        #pragma unroll
        for (int mt = 0; mt < 2; ++mt) {
            int r0 = mb + mt * 16 + g;
            uint2 w0 = *(const uint2*)(As + r0 * SMP + k0 + 2 * tig);
            uint2 w1 = *(const uint2*)(As + (r0 + 8) * SMP + k0 + 2 * tig);
            uint2 w2 = *(const uint2*)(As + r0 * SMP + k0 + 8 + 2 * tig);
            uint2 w3 = *(const uint2*)(As + (r0 + 8) * SMP + k0 + 8 + 2 * tig);
            ah[mt][0] = __byte_perm(w0.x, w0.y, 0x5410); al[mt][0] = __byte_perm(w0.x, w0.y, 0x7632);
            ah[mt][1] = __byte_perm(w1.x, w1.y, 0x5410); al[mt][1] = __byte_perm(w1.x, w1.y, 0x7632);
            ah[mt][2] = __byte_perm(w2.x, w2.y, 0x5410); al[mt][2] = __byte_perm(w2.x, w2.y, 0x7632);
            ah[mt][3] = __byte_perm(w3.x, w3.y, 0x5410); al[mt][3] = __byte_perm(w3.x, w3.y, 0x7632);
        }
        #pragma unroll
        for (int nt = 0; nt < 8; ++nt) {
            int o = nb + nt * 8 + g;
            uint2 u0 = *(const uint2*)(Ws + o * SMP + k0 + 2 * tig);
            uint2 u1 = *(const uint2*)(Ws + o * SMP + k0 + 8 + 2 * tig);
            uint32_t bh0 = __byte_perm(u0.x, u0.y, 0x5410);
            uint32_t bl0 = __byte_perm(u0.x, u0.y, 0x7632);
            uint32_t bh1 = __byte_perm(u1.x, u1.y, 0x5410);
            uint32_t bl1 = __byte_perm(u1.x, u1.y, 0x7632);
            #pragma unroll
            for (int mt = 0; mt < 2; ++mt) {
                mma_bf16(d[mt][nt], ah[mt], bh0, bh1);   // hi*hi
                mma_bf16(d[mt][nt], al[mt], bh0, bh1);   // lo*hi
                mma_bf16(d[mt][nt], ah[mt], bl0, bl1);   // hi*lo
            }
        }
    }

    // ---- stats: per-column sum / sumsq (padded rows contribute exact zeros) --
    if (STATS) {
        float s[8][2], q[8][2];
        #pragma unroll
        for (int nt = 0; nt < 8; ++nt)
            #pragma unroll
            for (int j = 0; j < 2; ++j) {
                float sv = 0.f, qv = 0.f;
                #pragma unroll
                for (int mt = 0; mt < 2; ++mt) {
                    float v0 = d[mt][nt][j], v1 = d[mt][nt][j + 2];
                    sv += v0 + v1;
                    qv = fmaf(v0, v0, fmaf(v1, v1, qv));
                }
                #pragma unroll
                for (int off = 4; off < 32; off <<= 1) {
                    sv += __shfl_xor_sync(0xffffffffu, sv, off);
                    qv += __shfl_xor_sync(0xffffffffu, qv, off);
                }
                s[nt][j] = sv; q[nt][j] = qv;
            }
        __syncthreads();                      // done reading As/Ws; reuse as Red
        float* RedS = (float*)sm;             // [8][64]
        float* RedQ = (float*)sm + 512;       // [8][64]
        if (g == 0) {
            #pragma unroll
            for (int nt = 0; nt < 8; ++nt)
                #pragma unroll
                for (int j = 0; j < 2; ++j) {
                    int lc = nt * 8 + tig * 2 + j;
                    RedS[w * 64 + lc] = s[nt][j];
                    RedQ[w * 64 + lc] = q[nt][j];
                }
        }
        __syncthreads();
        if (t < 128) {
            int gsel = t >> 6;         // n-group
            int lc = t & 63;
            float sv = 0.f, qv = 0.f;
            #pragma unroll
            for (int ww = 0; ww < 4; ++ww) {
                sv += RedS[(gsel * 4 + ww) * 64 + lc];
                qv += RedQ[(gsel * 4 + ww) * 64 + lc];
            }
            atomicAdd(&g_accs[gsel * 64 + lc], sv);
            atomicAdd(&g_accq[gsel * 64 + lc], qv);
        }
    }

    // ---- store C ----
    #pragma unroll
    for (int nt = 0; nt < 8; ++nt) {
        int col = nb + nt * 8 + tig * 2;
        float2 bb = make_float2(0.f, 0.f);
        if (BIAS) bb = *(const float2*)(bias + col);
        #pragma unroll
        for (int mt = 0; mt < 2; ++mt) {
            int r0 = m0 + mb + mt * 16 + g;
            if (r0 < storeN) {
                float2 v = make_float2(d[mt][nt][0] + bb.x, d[mt][nt][1] + bb.y);
                *(float2*)(out + (size_t)r0 * H + col) = v;
            }
            if (r0 + 8 < storeN) {
                float2 v = make_float2(d[mt][nt][2] + bb.x, d[mt][nt][3] + bb.y);
                *(float2*)(out + (size_t)(r0 + 8) * H + col) = v;
            }
        }
    }
}

// ---------------- BN coefficient kernels (1 block, 128 threads) ---------------
__global__ void stats1_k(const float* __restrict__ g, const float* __restrict__ b) {
    int t = threadIdx.x;
    float mu = g_accs[t] * (1.f / NNODE);
    float var = g_accq[t] * (1.f / NNODE) - mu * mu;
    float a = g[t] * rsqrtf(var + BN_EPS);
    g_ta[t] = a;
    g_ts[t] = b[t] - mu * a;
    g_accs[t] = 0.f; g_accq[t] = 0.f;
}

__global__ void stats2_k(const float* __restrict__ g2, const float* __restrict__ g3,
                         const float* __restrict__ b3) {
    int t = threadIdx.x;
    float mu = g_accs[t] * (1.f / NNODE);
    float var = g_accq[t] * (1.f / NNODE) - mu * mu;
    float r2 = rsqrtf(var + BN_EPS);
    float gr = g2[t] * r2;
    float v3 = gr * gr * var;
    float A = gr * g3[t] * rsqrtf(v3 + BN_EPS);
    g_ta[t] = A;
    g_ts[t] = b3[t] - mu * A;
    g_accs[t] = 0.f; g_accq[t] = 0.f;
}

// ---------------- launch ------------------------------------------------------
extern "C" void kernel_launch(void* const* d_in, const int* in_sizes, int n_in,
                              void* d_out, int out_size) {
    const float* x     = (const float*)d_in[0];
    const int*   ei    = (const int*)  d_in[1];
    const float* fc1_w = (const float*)d_in[2];
    const float* bn1_g = (const float*)d_in[4];
    const float* bn1_b = (const float*)d_in[5];
    const float* fc2_w = (const float*)d_in[6];
    const float* bn2_g = (const float*)d_in[8];
    const float* bn3_g = (const float*)d_in[10];
    const float* bn3_b = (const float*)d_in[11];
    const float* fc_w  = (const float*)d_in[12];
    const float* fc_b  = (const float*)d_in[13];
    float* out = (float*)d_out;

    cudaFuncSetAttribute(gemm_tc<false, true,  false>,
                         cudaFuncAttributeMaxDynamicSharedMemorySize, GEMM_SMEM_BYTES);
    cudaFuncSetAttribute(gemm_tc<true,  true,  false>,
                         cudaFuncAttributeMaxDynamicSharedMemorySize, GEMM_SMEM_BYTES);
    cudaFuncSetAttribute(gemm_tc<true,  false, true >,
                         cudaFuncAttributeMaxDynamicSharedMemorySize, GEMM_SMEM_BYTES);

    zero_k<<<(NNODE + 255) / 256, 256>>>();
    hist_k<<<(NEDGE + 255) / 256, 256>>>(ei + NEDGE);
    scan_k<<<1, 1024>>>();
    fill_k<<<(NEDGE + 255) / 256, 256>>>(ei);

    const int GEMM_GRID = HPAD / 128;   // 391
    const int AGG_GRID  = HPAD / 8;     // 6256

    for (int i = 0; i < LNUM; ++i) {
        if (i == 0) agg_k<false><<<AGG_GRID, 256>>>(x);
        else        agg_k<true ><<<AGG_GRID, 256>>>(nullptr);
        gemm_tc<false, true, false><<<GEMM_GRID, 256, GEMM_SMEM_BYTES>>>(
            0, fc1_w + (size_t)i * H * H, 0, nullptr, nullptr, HPAD);
        stats1_k<<<1, 128>>>(bn1_g + i * H, bn1_b + i * H);
        gemm_tc<true, true, false><<<GEMM_GRID, 256, GEMM_SMEM_BYTES>>>(
            1, fc2_w + (size_t)i * H * H, 1, nullptr, nullptr, HPAD);
        stats2_k<<<1, 128>>>(bn2_g + i * H, bn3_g + i * H, bn3_b + i * H);
    }
    gemm_tc<true, false, true><<<GEMM_GRID, 256, GEMM_SMEM_BYTES>>>(
        2, fc_w, 2, out, fc_b, NNODE);
}